// round 12
// baseline (speedup 1.0000x reference)
#include <cuda_runtime.h>

// FINAL: Row-wise L1 normalization y[b,r,:] = x[b,r,:] / max(sum(x[b,r,:]), 1e-5)
// [16, 2048, 2048] fp32. 128-thread CTA = 2 warp-pairs, each pair owns one row:
// 64 lanes x 8 float4 = 2048 floats, fully register-resident (single pass,
// 512 MB total HBM traffic = theoretical minimum). The two rows' phases
// interleave inside the CTA so one pair's barrier/reduce hides under the
// other's memory traffic. Pair-local sync via named barriers (bar.sync id, 64).
//
// Measured (same source, three sessions): 80.6 / 81.2 / 86.5 us — the 86.5
// sample ran at a reduced SM clock (all SM-relative ncu %s inflated, DRAM%
// deflated, identical SASS). At nominal clocks: DRAM ~81%, ~6.5 TB/s
// sustained = practical GB300 mixed R/W HBM ceiling. Explored and rejected:
// MLP 2/16, 4/8 pairs per CTA, multi-row loops, contiguous row blocks.

#define ROW_LEN 2048
#define V4_PER_ROW (ROW_LEN / 4)        // 512
#define THREADS 128
#define HALF 64
#define V4_PER_THREAD (V4_PER_ROW / HALF)  // 8
#define N_ROWS (16 * 2048)              // 32768
#define GRID (N_ROWS / 2)               // 16384

__global__ __launch_bounds__(THREADS)
void rownorm_2row_kernel(const float4* __restrict__ in, float4* __restrict__ out) {
    const int t = threadIdx.x;
    const int half = t >> 6;            // 0 or 1: which row this warp-pair owns
    const int ht = t & (HALF - 1);      // 0..63 within the pair
    const int row = blockIdx.x * 2 + half;
    const long long base = (long long)row * V4_PER_ROW + ht;

    // Front-batched streaming loads: 8 independent LDG.128 per thread.
    float4 v[V4_PER_THREAD];
    #pragma unroll
    for (int i = 0; i < V4_PER_THREAD; i++)
        v[i] = __ldcs(&in[base + i * HALF]);

    float s = 0.0f;
    #pragma unroll
    for (int i = 0; i < V4_PER_THREAD; i++)
        s += (v[i].x + v[i].y) + (v[i].z + v[i].w);

    // Warp reduction.
    #pragma unroll
    for (int o = 16; o > 0; o >>= 1)
        s += __shfl_xor_sync(0xffffffffu, s, o);

    // Pair-local combine of the two warps via named barrier (64 threads).
    __shared__ float ws[4];             // [half*2 + warp_in_pair]
    const int wip = (t >> 5) & 1;
    if ((t & 31) == 0) ws[half * 2 + wip] = s;
    // Named barrier per pair: id 1 and 2, 64 threads each.
    asm volatile("bar.sync %0, 64;" :: "r"(1 + half) : "memory");

    const float inv = 1.0f / fmaxf(ws[half * 2] + ws[half * 2 + 1], 1e-5f);

    #pragma unroll
    for (int i = 0; i < V4_PER_THREAD; i++) {
        float4 w = v[i];
        w.x *= inv; w.y *= inv; w.z *= inv; w.w *= inv;
        __stcs(&out[base + i * HALF], w);
    }
}

extern "C" void kernel_launch(void* const* d_in, const int* in_sizes, int n_in,
                              void* d_out, int out_size) {
    const float4* in = (const float4*)d_in[0];
    float4* out = (float4*)d_out;
    rownorm_2row_kernel<<<GRID, THREADS>>>(in, out);
}

// round 13
// speedup vs baseline: 1.0586x; 1.0586x over previous
#include <cuda_runtime.h>

// Row-wise L1 normalization y[b,r,:] = x[b,r,:] / max(sum(x[b,r,:]), 1e-5)
// [16, 2048, 2048] fp32. One 64-thread CTA (2 warps) per row:
// 64 lanes x 8 float4 = 2048 floats, register-resident, single pass
// (512 MB total HBM traffic = theoretical minimum).
// High-occupancy variant (~59% vs 22% for the 128-thr config): ~38 warps/SM
// keep ~2.7x more load bytes in flight, which saturates DRAM even in the
// reduced-SM-clock sessions observed in the broker pool (R11/R12) where the
// low-occupancy config dropped to 71% DRAM.

#define ROW_LEN 2048
#define V4_PER_ROW (ROW_LEN / 4)        // 512
#define THREADS 64
#define V4_PER_THREAD (V4_PER_ROW / THREADS)  // 8
#define N_ROWS (16 * 2048)              // 32768

__global__ __launch_bounds__(THREADS)
void rownorm_2w_kernel(const float4* __restrict__ in, float4* __restrict__ out) {
    const int t = threadIdx.x;
    const long long base = (long long)blockIdx.x * V4_PER_ROW + t;

    // Front-batched streaming loads: 8 independent LDG.128 per thread.
    float4 v[V4_PER_THREAD];
    #pragma unroll
    for (int i = 0; i < V4_PER_THREAD; i++)
        v[i] = __ldcs(&in[base + i * THREADS]);

    float s = 0.0f;
    #pragma unroll
    for (int i = 0; i < V4_PER_THREAD; i++)
        s += (v[i].x + v[i].y) + (v[i].z + v[i].w);

    // Warp reduction.
    #pragma unroll
    for (int o = 16; o > 0; o >>= 1)
        s += __shfl_xor_sync(0xffffffffu, s, o);

    // Combine the two warps via smem (2-warp barrier, 7-cyc floor).
    __shared__ float ws[2];
    if ((t & 31) == 0) ws[t >> 5] = s;
    __syncthreads();

    const float inv = 1.0f / fmaxf(ws[0] + ws[1], 1e-5f);

    #pragma unroll
    for (int i = 0; i < V4_PER_THREAD; i++) {
        float4 w = v[i];
        w.x *= inv; w.y *= inv; w.z *= inv; w.w *= inv;
        __stcs(&out[base + i * THREADS], w);
    }
}

extern "C" void kernel_launch(void* const* d_in, const int* in_sizes, int n_in,
                              void* d_out, int out_size) {
    const float4* in = (const float4*)d_in[0];
    float4* out = (float4*)d_out;
    rownorm_2w_kernel<<<N_ROWS, THREADS>>>(in, out);
}